// round 6
// baseline (speedup 1.0000x reference)
#include <cuda_runtime.h>
#include <cstdint>

// Problem constants
#define Bn   4
#define Cn   16
#define Hn   800
#define Wn   1200
#define HWn  (Hn * Wn)          // 960000
#define HFn  200                 // H/4
#define WFn  200                 // W/6
#define NPIX (512 * 512)         // 262144

// Part -> source selection: parts {1, 14..21} come from source_feature
#define SRC_MASK 0x003FC002u
// Apparel classes: cls==2 or 15<=cls<=22  -> bits 2, 15..22
#define APP_MASK 0x007F8004u

// XLA lowering of (x*199)/255: divide -> multiply by fl(1/255) = 0x3B808081,
// multiplies NOT reassociated (verified bit-exact in R3).
__device__ __forceinline__ float recip255() {
    return __uint_as_float(0x3B808081u);
}

struct PixCtx {
    int  pos;
    bool valid, apparel, bg;
    const float* fbase;
};

__device__ __forceinline__ PixCtx decode(const float* __restrict__ dp,
                                         const float* __restrict__ sf,
                                         const float* __restrict__ tf,
                                         int b, int pix)
{
    const float* d = dp + ((size_t)b * NPIX + pix) * 3;
    const float clsf = d[0];
    const float U    = d[1];
    const float V    = d[2];

    const int cls = (int)clsf;
    PixCtx c;
    c.valid   = (cls >= 1) && (V != 0.0f);
    c.apparel = (APP_MASK >> cls) & 1u;
    c.bg      = (cls != 0);

    int p = cls - 1;
    p = p < 0 ? 0 : (p > 23 ? 23 : p);

    const float R = recip255();
    const int ui = (int)__fmul_rn(__fmul_rn(U, 199.0f), R);
    const int vi = (int)__fmul_rn(__fmul_rn(__fsub_rn(255.0f, V), 199.0f), R);

    const int tr = p / 6;
    const int tc = p - tr * 6;
    c.pos = (tr * HFn + ui) * Wn + (tc * WFn + vi);

    const bool use_src = (SRC_MASK >> p) & 1u;
    c.fbase = (use_src ? sf : tf) + (size_t)b * Cn * HWn + c.pos;
    return c;
}

// ---------------------------------------------------------------------------
// Fused gather, 2 pixels per thread for 2x memory-level parallelism.
// Thread t in block handles pixels base+t and base+256+t (both coalesced for
// dense_pose reads and output writes).
// ---------------------------------------------------------------------------
__global__ __launch_bounds__(256) void k_fused2(
    const float* __restrict__ sf,    // source_feature [B,16,H,W]
    const float* __restrict__ tf,    // target_feature [B,16,H,W]
    const float* __restrict__ dp,    // dense_pose [B,512,512,3]
    const float* __restrict__ st,    // source_texture [B,3,H,W]
    const float* __restrict__ timg,  // target_image [B,3,512,512]
    float* __restrict__ out)         // [B,19,512,512]
{
    const int b    = blockIdx.y;
    const int base = blockIdx.x * 512;
    const int p0   = base + threadIdx.x;
    const int p1   = p0 + 256;

    const PixCtx c0 = decode(dp, sf, tf, b, p0);
    const PixCtx c1 = decode(dp, sf, tf, b, p1);

    // Issue ALL gather loads for both pixels up front (MLP ~ 38/thread).
    float v0[16], v1[16];
    if (c0.valid) {
#pragma unroll
        for (int ch = 0; ch < 16; ch++) v0[ch] = __ldg(c0.fbase + (size_t)ch * HWn);
    }
    if (c1.valid) {
#pragma unroll
        for (int ch = 0; ch < 16; ch++) v1[ch] = __ldg(c1.fbase + (size_t)ch * HWn);
    }

    float t0x = 0.f, t0y = 0.f, t0z = 0.f;
    float t1x = 0.f, t1y = 0.f, t1z = 0.f;
    if (c0.valid && c0.apparel) {
        const float* tb = st + (size_t)b * 3 * HWn + c0.pos;
        t0x = __ldg(tb); t0y = __ldg(tb + HWn); t0z = __ldg(tb + 2 * HWn);
    }
    if (c1.valid && c1.apparel) {
        const float* tb = st + (size_t)b * 3 * HWn + c1.pos;
        t1x = __ldg(tb); t1y = __ldg(tb + HWn); t1z = __ldg(tb + 2 * HWn);
    }

    if (!c0.valid) {
#pragma unroll
        for (int ch = 0; ch < 16; ch++) v0[ch] = 0.0f;
    }
    if (!c1.valid) {
#pragma unroll
        for (int ch = 0; ch < 16; ch++) v1[ch] = 0.0f;
    }

    float* ob0 = out + (size_t)b * 19 * NPIX + p0;
    float* ob1 = out + (size_t)b * 19 * NPIX + p1;
#pragma unroll
    for (int ch = 0; ch < 16; ch++) {
        ob0[(size_t)ch * NPIX] = v0[ch];
        ob1[(size_t)ch * NPIX] = v1[ch];
    }

    // Composite channels 16..18
    {
        const float* ti = timg + (size_t)b * 3 * NPIX + p0;
        float o16, o17, o18;
        if (c0.apparel)      { o16 = t0x; o17 = t0y; o18 = t0z; }
        else if (c0.bg)      { o16 = __ldg(ti); o17 = __ldg(ti + NPIX); o18 = __ldg(ti + 2 * NPIX); }
        else                 { o16 = 0.f; o17 = 0.f; o18 = 0.f; }
        ob0[16 * NPIX] = o16; ob0[17 * NPIX] = o17; ob0[18 * NPIX] = o18;
    }
    {
        const float* ti = timg + (size_t)b * 3 * NPIX + p1;
        float o16, o17, o18;
        if (c1.apparel)      { o16 = t1x; o17 = t1y; o18 = t1z; }
        else if (c1.bg)      { o16 = __ldg(ti); o17 = __ldg(ti + NPIX); o18 = __ldg(ti + 2 * NPIX); }
        else                 { o16 = 0.f; o17 = 0.f; o18 = 0.f; }
        ob1[16 * NPIX] = o16; ob1[17 * NPIX] = o17; ob1[18 * NPIX] = o18;
    }
}

// ---------------------------------------------------------------------------
extern "C" void kernel_launch(void* const* d_in, const int* in_sizes, int n_in,
                              void* d_out, int out_size)
{
    const float* source_feature = (const float*)d_in[0];
    const float* target_feature = (const float*)d_in[1];
    const float* dense_pose     = (const float*)d_in[2];
    const float* source_texture = (const float*)d_in[3];
    const float* target_image   = (const float*)d_in[4];
    float* out = (float*)d_out;

    dim3 g(NPIX / 512, Bn);
    k_fused2<<<g, 256>>>(source_feature, target_feature, dense_pose,
                         source_texture, target_image, out);
}

// round 8
// speedup vs baseline: 1.1941x; 1.1941x over previous
#include <cuda_runtime.h>
#include <cstdint>

// Problem constants
#define Bn   4
#define Cn   16
#define Hn   800
#define Wn   1200
#define HWn  (Hn * Wn)          // 960000
#define HFn  200                 // H/4
#define WFn  200                 // W/6
#define NPIX (512 * 512)         // 262144

// Part -> source selection: parts {1, 14..21} come from source_feature
#define SRC_MASK 0x003FC002u
// Apparel classes: cls==2 or 15<=cls<=22  -> bits 2, 15..22
#define APP_MASK 0x007F8004u

// XLA lowering of (x*199)/255: divide -> multiply by fl(1/255) = 0x3B808081,
// multiplies NOT reassociated (verified bit-exact in R3).
__device__ __forceinline__ float recip255() {
    return __uint_as_float(0x3B808081u);
}

// L2 evict_last cache policy (fractional, 100% of lines) — legal for scalar
// loads via the cache_hint form (inline .L2::evict_last is vector-only on sm_103).
__device__ __forceinline__ uint64_t mk_policy_keep() {
    uint64_t pol;
    asm("createpolicy.fractional.L2::evict_last.b64 %0, 1.0;" : "=l"(pol));
    return pol;
}

__device__ __forceinline__ float ldg_keep(const float* p, uint64_t pol) {
    float v;
    asm volatile("ld.global.nc.L2::cache_hint.f32 %0, [%1], %2;"
                 : "=f"(v) : "l"(p), "l"(pol));
    return v;
}

// ---------------------------------------------------------------------------
// Fused gather kernel (R4 structure):
//  - 1 pixel / thread, 256 threads
//  - gathers: L2 evict_last via cache policy (protect random-sector reuse)
//  - streams: evict_first (__ldcs / __stcs)
// ---------------------------------------------------------------------------
__global__ __launch_bounds__(256) void k_fused(
    const float* __restrict__ sf,    // source_feature [B,16,H,W]
    const float* __restrict__ tf,    // target_feature [B,16,H,W]
    const float* __restrict__ dp,    // dense_pose [B,512,512,3]
    const float* __restrict__ st,    // source_texture [B,3,H,W]
    const float* __restrict__ timg,  // target_image [B,3,512,512]
    float* __restrict__ out)         // [B,19,512,512]
{
    const int b   = blockIdx.y;
    const int pix = blockIdx.x * 256 + threadIdx.x;   // 0 .. NPIX-1

    const float* d = dp + ((size_t)b * NPIX + pix) * 3;
    const float clsf = __ldcs(d);
    const float U    = __ldcs(d + 1);
    const float V    = __ldcs(d + 2);

    const int  cls   = (int)clsf;
    const bool valid = (cls >= 1) && (V != 0.0f);

    int p = cls - 1;
    p = p < 0 ? 0 : (p > 23 ? 23 : p);

    const float R = recip255();
    // XLA: t = RN(x*199); idx = trunc(RN(t * fl(1/255)))
    const int ui = (int)__fmul_rn(__fmul_rn(U, 199.0f), R);
    const int vi = (int)__fmul_rn(__fmul_rn(__fsub_rn(255.0f, V), 199.0f), R);

    const int tr  = p / 6;
    const int tc  = p - tr * 6;
    const int pos = (tr * HFn + ui) * Wn + (tc * WFn + vi);

    // Union selection: which tensor does this PART come from
    const bool use_src = (SRC_MASK >> p) & 1u;
    const float* fbase = (use_src ? sf : tf) + (size_t)b * Cn * HWn + pos;

    const bool apparel = (APP_MASK >> cls) & 1u;   // implies cls != 0
    const bool bg      = (cls != 0);

    const uint64_t pol = mk_policy_keep();

    float v[16];
    float t0 = 0.f, t1 = 0.f, t2 = 0.f;
    if (valid) {
#pragma unroll
        for (int ch = 0; ch < 16; ch++)
            v[ch] = ldg_keep(fbase + (size_t)ch * HWn, pol);
        if (apparel) {
            const float* tb = st + (size_t)b * 3 * HWn + pos;
            t0 = ldg_keep(tb, pol);
            t1 = ldg_keep(tb + HWn, pol);
            t2 = ldg_keep(tb + 2 * HWn, pol);
        }
    } else {
#pragma unroll
        for (int ch = 0; ch < 16; ch++)
            v[ch] = 0.0f;
    }

    float* ob = out + (size_t)b * 19 * NPIX + pix;
#pragma unroll
    for (int ch = 0; ch < 16; ch++)
        __stcs(ob + (size_t)ch * NPIX, v[ch]);

    if (apparel) {
        __stcs(ob + 16 * NPIX, t0);
        __stcs(ob + 17 * NPIX, t1);
        __stcs(ob + 18 * NPIX, t2);
    } else if (bg) {
        const float* ti = timg + (size_t)b * 3 * NPIX + pix;
        __stcs(ob + 16 * NPIX, __ldcs(ti));
        __stcs(ob + 17 * NPIX, __ldcs(ti + NPIX));
        __stcs(ob + 18 * NPIX, __ldcs(ti + 2 * NPIX));
    } else {
        __stcs(ob + 16 * NPIX, 0.0f);
        __stcs(ob + 17 * NPIX, 0.0f);
        __stcs(ob + 18 * NPIX, 0.0f);
    }
}

// ---------------------------------------------------------------------------
extern "C" void kernel_launch(void* const* d_in, const int* in_sizes, int n_in,
                              void* d_out, int out_size)
{
    const float* source_feature = (const float*)d_in[0];
    const float* target_feature = (const float*)d_in[1];
    const float* dense_pose     = (const float*)d_in[2];
    const float* source_texture = (const float*)d_in[3];
    const float* target_image   = (const float*)d_in[4];
    float* out = (float*)d_out;

    dim3 g(NPIX / 256, Bn);
    k_fused<<<g, 256>>>(source_feature, target_feature, dense_pose,
                        source_texture, target_image, out);
}